// round 2
// baseline (speedup 1.0000x reference)
#include <cuda_runtime.h>
#include <cuda_bf16.h>

#define NPTS 65536
#define CIN  256
#define COUT 512
#define KNN  16
#define LN_EPS 1e-5f

// Scratch (allocation-free requirement -> __device__ globals)
__device__ float g_X[(size_t)NPTS * CIN];   // 64 MB: LayerNormed feats
__device__ float g_P[(size_t)NPTS * COUT];  // 128 MB: projected feats

// ---------------------------------------------------------------------------
// K1: per-row LayerNorm.  One warp per row (256 channels = 8 floats/lane).
// ---------------------------------------------------------------------------
__global__ void ln_kernel(const float* __restrict__ feats,
                          const float* __restrict__ w,
                          const float* __restrict__ b) {
    int row  = blockIdx.x * 8 + (threadIdx.x >> 5);
    int lane = threadIdx.x & 31;
    const float4* src = reinterpret_cast<const float4*>(feats) + (size_t)row * (CIN / 4);
    float4 v0 = src[lane];
    float4 v1 = src[lane + 32];

    float s = v0.x + v0.y + v0.z + v0.w + v1.x + v1.y + v1.z + v1.w;
    #pragma unroll
    for (int o = 16; o; o >>= 1) s += __shfl_xor_sync(0xffffffffu, s, o);
    float mu = s * (1.0f / CIN);

    float d0 = v0.x - mu, d1 = v0.y - mu, d2 = v0.z - mu, d3 = v0.w - mu;
    float d4 = v1.x - mu, d5 = v1.y - mu, d6 = v1.z - mu, d7 = v1.w - mu;
    float ss = d0*d0 + d1*d1 + d2*d2 + d3*d3 + d4*d4 + d5*d5 + d6*d6 + d7*d7;
    #pragma unroll
    for (int o = 16; o; o >>= 1) ss += __shfl_xor_sync(0xffffffffu, ss, o);
    float r = rsqrtf(ss * (1.0f / CIN) + LN_EPS);

    const float4* w4 = reinterpret_cast<const float4*>(w);
    const float4* b4 = reinterpret_cast<const float4*>(b);
    float4 W0 = w4[lane], W1 = w4[lane + 32];
    float4 B0 = b4[lane], B1 = b4[lane + 32];

    float4 o0, o1;
    o0.x = d0 * r * W0.x + B0.x;  o0.y = d1 * r * W0.y + B0.y;
    o0.z = d2 * r * W0.z + B0.z;  o0.w = d3 * r * W0.w + B0.w;
    o1.x = d4 * r * W1.x + B1.x;  o1.y = d5 * r * W1.y + B1.y;
    o1.z = d6 * r * W1.z + B1.z;  o1.w = d7 * r * W1.w + B1.w;

    float4* dst = reinterpret_cast<float4*>(g_X) + (size_t)row * (CIN / 4);
    dst[lane]      = o0;
    dst[lane + 32] = o1;
}

// ---------------------------------------------------------------------------
// K2: P = X (NPTS x CIN) @ W^T (CIN x COUT).  128x128 tile, TK=8, 8x8 micro.
// ---------------------------------------------------------------------------
#define TM 128
#define TN 128
#define TK 8

__global__ __launch_bounds__(256) void gemm_kernel(const float* __restrict__ Wmat) {
    __shared__ float As[TK][TM];
    __shared__ float Bs[TK][TN];

    int bm  = blockIdx.x;          // 512 tiles over NPTS
    int bn  = blockIdx.y;          // 4 tiles over COUT
    int tid = threadIdx.x;         // 256
    int tx  = tid & 15;            // 16 n-groups of 8
    int ty  = tid >> 4;            // 16 m-groups of 8

    float acc[8][8];
    #pragma unroll
    for (int i = 0; i < 8; i++)
        #pragma unroll
        for (int j = 0; j < 8; j++) acc[i][j] = 0.0f;

    const float* Aptr = g_X  + (size_t)(bm * TM) * CIN;
    const float* Bptr = Wmat + (size_t)(bn * TN) * CIN;

    int lr = tid >> 1;             // 0..127 : row within tile
    int lk = (tid & 1) * 4;        // 0 or 4 : k sub-chunk

    for (int k0 = 0; k0 < CIN; k0 += TK) {
        float4 av = *reinterpret_cast<const float4*>(Aptr + (size_t)lr * CIN + k0 + lk);
        float4 bv = *reinterpret_cast<const float4*>(Bptr + (size_t)lr * CIN + k0 + lk);
        __syncthreads();
        As[lk + 0][lr] = av.x; As[lk + 1][lr] = av.y;
        As[lk + 2][lr] = av.z; As[lk + 3][lr] = av.w;
        Bs[lk + 0][lr] = bv.x; Bs[lk + 1][lr] = bv.y;
        Bs[lk + 2][lr] = bv.z; Bs[lk + 3][lr] = bv.w;
        __syncthreads();

        #pragma unroll
        for (int k = 0; k < TK; k++) {
            float a[8], bb[8];
            *reinterpret_cast<float4*>(&a[0])  = *reinterpret_cast<const float4*>(&As[k][ty * 8]);
            *reinterpret_cast<float4*>(&a[4])  = *reinterpret_cast<const float4*>(&As[k][ty * 8 + 4]);
            *reinterpret_cast<float4*>(&bb[0]) = *reinterpret_cast<const float4*>(&Bs[k][tx * 8]);
            *reinterpret_cast<float4*>(&bb[4]) = *reinterpret_cast<const float4*>(&Bs[k][tx * 8 + 4]);
            #pragma unroll
            for (int i = 0; i < 8; i++)
                #pragma unroll
                for (int j = 0; j < 8; j++)
                    acc[i][j] += a[i] * bb[j];
        }
    }

    float* outp = g_P + (size_t)(bm * TM + ty * 8) * COUT + bn * TN + tx * 8;
    #pragma unroll
    for (int i = 0; i < 8; i++) {
        *reinterpret_cast<float4*>(outp + (size_t)i * COUT)     =
            make_float4(acc[i][0], acc[i][1], acc[i][2], acc[i][3]);
        *reinterpret_cast<float4*>(outp + (size_t)i * COUT + 4) =
            make_float4(acc[i][4], acc[i][5], acc[i][6], acc[i][7]);
    }
}

// ---------------------------------------------------------------------------
// K3: out[m, o] = max_k P[knn[m,k], o]; also n_xyz gather and n_offset.
// Output layout: [ n_xyz (3*M) | out (M*COUT) | n_offset (1) ]  (fp32)
// NOTE: the out section starts at float offset 3*M which is NOT 16B-aligned,
// so all d_out accesses here are scalar. Thread t covers channels t+128*j.
// ---------------------------------------------------------------------------
__global__ void pool_kernel(const float* __restrict__ xyz,
                            const int* __restrict__ samp,
                            const int* __restrict__ knn,
                            const int* __restrict__ offset,
                            float* __restrict__ out,
                            int m_total) {
    int m = blockIdx.x;
    int t = threadIdx.x;           // 128 threads, each handles 4 channels

    const int* kn = knn + (size_t)m * KNN;
    int idx[KNN];
    #pragma unroll
    for (int k = 0; k < KNN; k++) idx[k] = kn[k];

    float best[4] = {-3.4e38f, -3.4e38f, -3.4e38f, -3.4e38f};
    #pragma unroll
    for (int k = 0; k < KNN; k++) {
        const float* row = g_P + (size_t)idx[k] * COUT;
        #pragma unroll
        for (int j = 0; j < 4; j++)
            best[j] = fmaxf(best[j], row[t + j * 128]);
    }

    float* osec = out + (size_t)3 * m_total + (size_t)m * COUT;
    #pragma unroll
    for (int j = 0; j < 4; j++)
        osec[t + j * 128] = best[j];

    if (t < 3) {
        out[(size_t)m * 3 + t] = xyz[(size_t)samp[m] * 3 + t];
    }
    if (m == 0 && t == 3) {
        // n_offset = int(offset * 0.25) + 1
        out[(size_t)3 * m_total + (size_t)m_total * COUT] = (float)(offset[0] / 4 + 1);
    }
}

// ---------------------------------------------------------------------------
extern "C" void kernel_launch(void* const* d_in, const int* in_sizes, int n_in,
                              void* d_out, int out_size) {
    const float* xyz   = (const float*)d_in[0];
    const float* feats = (const float*)d_in[1];
    const float* nw    = (const float*)d_in[2];
    const float* nb    = (const float*)d_in[3];
    const float* lw    = (const float*)d_in[4];
    const int*   samp  = (const int*)d_in[5];
    const int*   knn   = (const int*)d_in[6];
    const int*   off   = (const int*)d_in[7];
    float* out = (float*)d_out;

    int M = in_sizes[5];           // 16385

    ln_kernel<<<NPTS / 8, 256>>>(feats, nw, nb);

    dim3 ggrid(NPTS / TM, COUT / TN);
    gemm_kernel<<<ggrid, 256>>>(lw);

    pool_kernel<<<M, 128>>>(xyz, samp, knn, off, out, M);
}

// round 5
// speedup vs baseline: 1.8677x; 1.8677x over previous
#include <cuda_runtime.h>
#include <cuda_bf16.h>
#include <cstdint>

#define NPTS 65536
#define CIN  256
#define COUT 512
#define KNN  16
#define LN_EPS 1e-5f

// Scratch (allocation-free requirement -> __device__ globals)
__device__ float g_X[(size_t)NPTS * CIN];   // 64 MB: LayerNormed feats
__device__ float g_P[(size_t)NPTS * COUT];  // 128 MB: projected feats

// ---------------------------------------------------------------------------
// K1: per-row LayerNorm.  One warp per row (256 channels = 8 floats/lane).
// ---------------------------------------------------------------------------
__global__ void ln_kernel(const float* __restrict__ feats,
                          const float* __restrict__ w,
                          const float* __restrict__ b) {
    int row  = blockIdx.x * 8 + (threadIdx.x >> 5);
    int lane = threadIdx.x & 31;
    const float4* src = reinterpret_cast<const float4*>(feats) + (size_t)row * (CIN / 4);
    float4 v0 = src[lane];
    float4 v1 = src[lane + 32];

    float s = v0.x + v0.y + v0.z + v0.w + v1.x + v1.y + v1.z + v1.w;
    #pragma unroll
    for (int o = 16; o; o >>= 1) s += __shfl_xor_sync(0xffffffffu, s, o);
    float mu = s * (1.0f / CIN);

    float d0 = v0.x - mu, d1 = v0.y - mu, d2 = v0.z - mu, d3 = v0.w - mu;
    float d4 = v1.x - mu, d5 = v1.y - mu, d6 = v1.z - mu, d7 = v1.w - mu;
    float ss = d0*d0 + d1*d1 + d2*d2 + d3*d3 + d4*d4 + d5*d5 + d6*d6 + d7*d7;
    #pragma unroll
    for (int o = 16; o; o >>= 1) ss += __shfl_xor_sync(0xffffffffu, ss, o);
    float r = rsqrtf(ss * (1.0f / CIN) + LN_EPS);

    const float4* w4 = reinterpret_cast<const float4*>(w);
    const float4* b4 = reinterpret_cast<const float4*>(b);
    float4 W0 = w4[lane], W1 = w4[lane + 32];
    float4 B0 = b4[lane], B1 = b4[lane + 32];

    float4 o0, o1;
    o0.x = d0 * r * W0.x + B0.x;  o0.y = d1 * r * W0.y + B0.y;
    o0.z = d2 * r * W0.z + B0.z;  o0.w = d3 * r * W0.w + B0.w;
    o1.x = d4 * r * W1.x + B1.x;  o1.y = d5 * r * W1.y + B1.y;
    o1.z = d6 * r * W1.z + B1.z;  o1.w = d7 * r * W1.w + B1.w;

    float4* dst = reinterpret_cast<float4*>(g_X) + (size_t)row * (CIN / 4);
    dst[lane]      = o0;
    dst[lane + 32] = o1;
}

// ---------------------------------------------------------------------------
// K2: tensor-core GEMM via mma.sync.m16n8k8.tf32 (arch-agnostic PTX).
// P = X (NPTS x CIN) @ W^T.  CTA tile 128x128, 8 warps of 64x32.
// Tiles staged row-major, stride 36 floats (pad 4) -> conflict-free LDS.
// ---------------------------------------------------------------------------
#define KCHUNK 32
#define NCHUNK (CIN / KCHUNK)     // 8
#define TSTRIDE 36                // 32 + 4 pad floats
#define TILE_FLOATS (128 * TSTRIDE)
#define SMEM_GEMM_BYTES (4 * TILE_FLOATS * 4)   // A0,A1,B0,B1 = 73728 B

__device__ __forceinline__ uint32_t cvt_tf32(float x) {
    uint32_t r;
    asm("cvt.rna.tf32.f32 %0, %1;" : "=r"(r) : "f"(x));
    return r;
}

__device__ __forceinline__ void mma_tf32(float& c0, float& c1, float& c2, float& c3,
                                         uint32_t a0, uint32_t a1, uint32_t a2, uint32_t a3,
                                         uint32_t b0, uint32_t b1) {
    asm volatile(
        "mma.sync.aligned.m16n8k8.row.col.f32.tf32.tf32.f32 "
        "{%0,%1,%2,%3}, {%4,%5,%6,%7}, {%8,%9}, {%0,%1,%2,%3};"
        : "+f"(c0), "+f"(c1), "+f"(c2), "+f"(c3)
        : "r"(a0), "r"(a1), "r"(a2), "r"(a3), "r"(b0), "r"(b1));
}

__global__ __launch_bounds__(256) void gemm_mma_kernel(const float* __restrict__ Wmat) {
    extern __shared__ float smem[];
    float* As[2] = { smem,                  smem + TILE_FLOATS };
    float* Bs[2] = { smem + 2 * TILE_FLOATS, smem + 3 * TILE_FLOATS };

    int tid  = threadIdx.x;
    int lane = tid & 31;
    int wid  = tid >> 5;
    int g    = lane >> 2;     // 0..7
    int tg   = lane & 3;      // 0..3
    int warp_m = (wid & 1) * 64;
    int warp_n = (wid >> 1) * 32;

    int bm = blockIdx.x;
    int bn = blockIdx.y;
    const float* Abase = g_X  + (size_t)(bm * 128) * CIN;
    const float* Bbase = Wmat + (size_t)(bn * 128) * CIN;

    // staging coords: each thread handles 4 float4s per tile
    int srow = tid >> 3;            // 0..31 (plus +32*i)
    int sk4  = (tid & 7) * 4;       // 0,4,...,28

    float acc[4][4][4];
    #pragma unroll
    for (int i = 0; i < 4; i++)
        #pragma unroll
        for (int j = 0; j < 4; j++)
            #pragma unroll
            for (int q = 0; q < 4; q++) acc[i][j][q] = 0.0f;

    float4 pa[4], pb[4];

    // prologue: load chunk 0
    #pragma unroll
    for (int i = 0; i < 4; i++) {
        int row = srow + 32 * i;
        pa[i] = *reinterpret_cast<const float4*>(Abase + (size_t)row * CIN + sk4);
        pb[i] = *reinterpret_cast<const float4*>(Bbase + (size_t)row * CIN + sk4);
    }
    #pragma unroll
    for (int i = 0; i < 4; i++) {
        int row = srow + 32 * i;
        uint32_t* ad = reinterpret_cast<uint32_t*>(As[0] + row * TSTRIDE + sk4);
        uint32_t* bd = reinterpret_cast<uint32_t*>(Bs[0] + row * TSTRIDE + sk4);
        ad[0] = cvt_tf32(pa[i].x); ad[1] = cvt_tf32(pa[i].y);
        ad[2] = cvt_tf32(pa[i].z); ad[3] = cvt_tf32(pa[i].w);
        bd[0] = cvt_tf32(pb[i].x); bd[1] = cvt_tf32(pb[i].y);
        bd[2] = cvt_tf32(pb[i].z); bd[3] = cvt_tf32(pb[i].w);
    }
    __syncthreads();

    for (int c = 0; c < NCHUNK; c++) {
        int buf = c & 1;
        // prefetch next chunk into registers (overlaps with MMA below)
        if (c + 1 < NCHUNK) {
            int k0 = (c + 1) * KCHUNK;
            #pragma unroll
            for (int i = 0; i < 4; i++) {
                int row = srow + 32 * i;
                pa[i] = *reinterpret_cast<const float4*>(Abase + (size_t)row * CIN + k0 + sk4);
                pb[i] = *reinterpret_cast<const float4*>(Bbase + (size_t)row * CIN + k0 + sk4);
            }
        }

        const float* Aw = As[buf];
        const float* Bw = Bs[buf];
        #pragma unroll
        for (int k8 = 0; k8 < KCHUNK; k8 += 8) {
            uint32_t a[4][4], b[4][2];
            #pragma unroll
            for (int mt = 0; mt < 4; mt++) {
                int rb = warp_m + mt * 16 + g;
                a[mt][0] = __float_as_uint(Aw[rb * TSTRIDE + k8 + tg]);
                a[mt][1] = __float_as_uint(Aw[(rb + 8) * TSTRIDE + k8 + tg]);
                a[mt][2] = __float_as_uint(Aw[rb * TSTRIDE + k8 + tg + 4]);
                a[mt][3] = __float_as_uint(Aw[(rb + 8) * TSTRIDE + k8 + tg + 4]);
            }
            #pragma unroll
            for (int nt = 0; nt < 4; nt++) {
                int nb = warp_n + nt * 8 + g;
                b[nt][0] = __float_as_uint(Bw[nb * TSTRIDE + k8 + tg]);
                b[nt][1] = __float_as_uint(Bw[nb * TSTRIDE + k8 + tg + 4]);
            }
            #pragma unroll
            for (int mt = 0; mt < 4; mt++)
                #pragma unroll
                for (int nt = 0; nt < 4; nt++)
                    mma_tf32(acc[mt][nt][0], acc[mt][nt][1], acc[mt][nt][2], acc[mt][nt][3],
                             a[mt][0], a[mt][1], a[mt][2], a[mt][3],
                             b[nt][0], b[nt][1]);
        }

        if (c + 1 < NCHUNK) {
            __syncthreads();   // everyone done reading buf^1 from 2 chunks ago
            int nbuf = buf ^ 1;
            #pragma unroll
            for (int i = 0; i < 4; i++) {
                int row = srow + 32 * i;
                uint32_t* ad = reinterpret_cast<uint32_t*>(As[nbuf] + row * TSTRIDE + sk4);
                uint32_t* bd = reinterpret_cast<uint32_t*>(Bs[nbuf] + row * TSTRIDE + sk4);
                ad[0] = cvt_tf32(pa[i].x); ad[1] = cvt_tf32(pa[i].y);
                ad[2] = cvt_tf32(pa[i].z); ad[3] = cvt_tf32(pa[i].w);
                bd[0] = cvt_tf32(pb[i].x); bd[1] = cvt_tf32(pb[i].y);
                bd[2] = cvt_tf32(pb[i].z); bd[3] = cvt_tf32(pb[i].w);
            }
            __syncthreads();
        }
    }

    // epilogue: c0,c1 -> (row=g, col=2tg, 2tg+1); c2,c3 -> row+8
    #pragma unroll
    for (int mt = 0; mt < 4; mt++) {
        int row = bm * 128 + warp_m + mt * 16 + g;
        #pragma unroll
        for (int nt = 0; nt < 4; nt++) {
            int col = bn * 128 + warp_n + nt * 8 + 2 * tg;
            float2* p0 = reinterpret_cast<float2*>(g_P + (size_t)row * COUT + col);
            float2* p1 = reinterpret_cast<float2*>(g_P + (size_t)(row + 8) * COUT + col);
            *p0 = make_float2(acc[mt][nt][0], acc[mt][nt][1]);
            *p1 = make_float2(acc[mt][nt][2], acc[mt][nt][3]);
        }
    }
}

// ---------------------------------------------------------------------------
// K3: out[m, o] = max_k P[knn[m,k], o]; also n_xyz gather and n_offset.
// Output layout: [ n_xyz (3*M) | out (M*COUT) | n_offset (1) ]  (fp32)
// out section starts at float offset 3*M (not 16B-aligned) -> scalar stores.
// ---------------------------------------------------------------------------
__global__ void pool_kernel(const float* __restrict__ xyz,
                            const int* __restrict__ samp,
                            const int* __restrict__ knn,
                            const int* __restrict__ offset,
                            float* __restrict__ out,
                            int m_total) {
    int m = blockIdx.x;
    int t = threadIdx.x;           // 128 threads, each handles 4 channels

    const int* kn = knn + (size_t)m * KNN;
    int idx[KNN];
    #pragma unroll
    for (int k = 0; k < KNN; k++) idx[k] = kn[k];

    float best[4] = {-3.4e38f, -3.4e38f, -3.4e38f, -3.4e38f};
    #pragma unroll
    for (int k = 0; k < KNN; k++) {
        const float* row = g_P + (size_t)idx[k] * COUT;
        #pragma unroll
        for (int j = 0; j < 4; j++)
            best[j] = fmaxf(best[j], row[t + j * 128]);
    }

    float* osec = out + (size_t)3 * m_total + (size_t)m * COUT;
    #pragma unroll
    for (int j = 0; j < 4; j++)
        osec[t + j * 128] = best[j];

    if (t < 3) {
        out[(size_t)m * 3 + t] = xyz[(size_t)samp[m] * 3 + t];
    }
    if (m == 0 && t == 3) {
        out[(size_t)3 * m_total + (size_t)m_total * COUT] = (float)(offset[0] / 4 + 1);
    }
}

// ---------------------------------------------------------------------------
extern "C" void kernel_launch(void* const* d_in, const int* in_sizes, int n_in,
                              void* d_out, int out_size) {
    const float* xyz   = (const float*)d_in[0];
    const float* feats = (const float*)d_in[1];
    const float* nw    = (const float*)d_in[2];
    const float* nb    = (const float*)d_in[3];
    const float* lw    = (const float*)d_in[4];
    const int*   samp  = (const int*)d_in[5];
    const int*   knn   = (const int*)d_in[6];
    const int*   off   = (const int*)d_in[7];
    float* out = (float*)d_out;

    int M = in_sizes[5];           // 16385

    cudaFuncSetAttribute(gemm_mma_kernel,
                         cudaFuncAttributeMaxDynamicSharedMemorySize,
                         SMEM_GEMM_BYTES);

    ln_kernel<<<NPTS / 8, 256>>>(feats, nw, nb);

    dim3 ggrid(NPTS / 128, COUT / 128);   // (512, 4)
    gemm_mma_kernel<<<ggrid, 256, SMEM_GEMM_BYTES>>>(lw);

    pool_kernel<<<M, 128>>>(xyz, samp, knn, off, out, M);
}

// round 7
// speedup vs baseline: 2.5352x; 1.3574x over previous
#include <cuda_runtime.h>
#include <cuda_bf16.h>
#include <cstdint>

#define NPTS 65536
#define CIN  256
#define COUT 512
#define KNN  16
#define LN_EPS 1e-5f

// Scratch (allocation-free requirement -> __device__ globals)
__device__ float g_X[(size_t)NPTS * CIN];   // 64 MB: LayerNormed feats (tf32-rounded)
__device__ float g_W[(size_t)COUT * CIN];   // 512 KB: tf32-rounded weights
__device__ float g_P[(size_t)NPTS * COUT];  // 128 MB: projected feats

__device__ __forceinline__ uint32_t smem_to_u32(const void* p) {
    uint32_t a;
    asm("{ .reg .u64 t; cvta.to.shared.u64 t, %1; cvt.u32.u64 %0, t; }" : "=r"(a) : "l"(p));
    return a;
}

__device__ __forceinline__ float cvt_tf32f(float x) {
    uint32_t r;
    asm("cvt.rna.tf32.f32 %0, %1;" : "=r"(r) : "f"(x));
    return __uint_as_float(r);
}

__device__ __forceinline__ void cpa16(uint32_t dst, const float* src) {
    asm volatile("cp.async.cg.shared.global [%0], [%1], 16;" :: "r"(dst), "l"(src));
}
#define CP_COMMIT() asm volatile("cp.async.commit_group;" ::: "memory")
#define CP_WAIT(n)  asm volatile("cp.async.wait_group %0;" :: "n"(n) : "memory")

__device__ __forceinline__ void mma_tf32(float& c0, float& c1, float& c2, float& c3,
                                         uint32_t a0, uint32_t a1, uint32_t a2, uint32_t a3,
                                         uint32_t b0, uint32_t b1) {
    asm volatile(
        "mma.sync.aligned.m16n8k8.row.col.f32.tf32.tf32.f32 "
        "{%0,%1,%2,%3}, {%4,%5,%6,%7}, {%8,%9}, {%0,%1,%2,%3};"
        : "+f"(c0), "+f"(c1), "+f"(c2), "+f"(c3)
        : "r"(a0), "r"(a1), "r"(a2), "r"(a3), "r"(b0), "r"(b1));
}

// ---------------------------------------------------------------------------
// K0: round W to tf32 once.
// ---------------------------------------------------------------------------
__global__ void wcvt_kernel(const float* __restrict__ W) {
    int i = blockIdx.x * 256 + threadIdx.x;             // COUT*CIN/4 = 32768 float4
    float4 v = reinterpret_cast<const float4*>(W)[i];
    v.x = cvt_tf32f(v.x); v.y = cvt_tf32f(v.y);
    v.z = cvt_tf32f(v.z); v.w = cvt_tf32f(v.w);
    reinterpret_cast<float4*>(g_W)[i] = v;
}

// ---------------------------------------------------------------------------
// K1: per-row LayerNorm, output rounded to tf32.  One warp per row.
// ---------------------------------------------------------------------------
__global__ void ln_kernel(const float* __restrict__ feats,
                          const float* __restrict__ w,
                          const float* __restrict__ b) {
    int row  = blockIdx.x * 8 + (threadIdx.x >> 5);
    int lane = threadIdx.x & 31;
    const float4* src = reinterpret_cast<const float4*>(feats) + (size_t)row * (CIN / 4);
    float4 v0 = src[lane];
    float4 v1 = src[lane + 32];

    float s = v0.x + v0.y + v0.z + v0.w + v1.x + v1.y + v1.z + v1.w;
    #pragma unroll
    for (int o = 16; o; o >>= 1) s += __shfl_xor_sync(0xffffffffu, s, o);
    float mu = s * (1.0f / CIN);

    float d0 = v0.x - mu, d1 = v0.y - mu, d2 = v0.z - mu, d3 = v0.w - mu;
    float d4 = v1.x - mu, d5 = v1.y - mu, d6 = v1.z - mu, d7 = v1.w - mu;
    float ss = d0*d0 + d1*d1 + d2*d2 + d3*d3 + d4*d4 + d5*d5 + d6*d6 + d7*d7;
    #pragma unroll
    for (int o = 16; o; o >>= 1) ss += __shfl_xor_sync(0xffffffffu, ss, o);
    float r = rsqrtf(ss * (1.0f / CIN) + LN_EPS);

    const float4* w4 = reinterpret_cast<const float4*>(w);
    const float4* b4 = reinterpret_cast<const float4*>(b);
    float4 W0 = w4[lane], W1 = w4[lane + 32];
    float4 B0 = b4[lane], B1 = b4[lane + 32];

    float4 o0, o1;
    o0.x = cvt_tf32f(d0 * r * W0.x + B0.x);  o0.y = cvt_tf32f(d1 * r * W0.y + B0.y);
    o0.z = cvt_tf32f(d2 * r * W0.z + B0.z);  o0.w = cvt_tf32f(d3 * r * W0.w + B0.w);
    o1.x = cvt_tf32f(d4 * r * W1.x + B1.x);  o1.y = cvt_tf32f(d5 * r * W1.y + B1.y);
    o1.z = cvt_tf32f(d6 * r * W1.z + B1.z);  o1.w = cvt_tf32f(d7 * r * W1.w + B1.w);

    float4* dst = reinterpret_cast<float4*>(g_X) + (size_t)row * (CIN / 4);
    dst[lane]      = o0;
    dst[lane + 32] = o1;
}

// ---------------------------------------------------------------------------
// K2: tf32 mma.sync GEMM.  P = X (NPTS x CIN) @ W^T.
// CTA tile 128x256, 8 warps of 64x64 (2x4).  cp.async double-buffered chunks.
// grid = (COUT/256, NPTS/128) = (2, 512): bn fastest -> A tiles L2-shared.
// ---------------------------------------------------------------------------
#define KCHUNK 32
#define NCHUNK (CIN / KCHUNK)     // 8
#define TSTRIDE 36
#define AOFF0 0
#define AOFF1 (128 * TSTRIDE)                 // 4608
#define BOFF0 (2 * 128 * TSTRIDE)             // 9216
#define BOFF1 (BOFF0 + 256 * TSTRIDE)         // 18432
#define SMEM_GEMM_FLOATS (BOFF1 + 256 * TSTRIDE)   // 27648
#define SMEM_GEMM_BYTES (SMEM_GEMM_FLOATS * 4)     // 110592

__global__ __launch_bounds__(256, 1) void gemm_mma_kernel() {
    extern __shared__ float smem[];
    uint32_t sb = smem_to_u32(smem);

    int tid  = threadIdx.x;
    int lane = tid & 31;
    int wid  = tid >> 5;
    int g    = lane >> 2;     // 0..7
    int tg   = lane & 3;      // 0..3
    int warp_m = (wid & 1) * 64;
    int warp_n = (wid >> 1) * 64;

    int bn = blockIdx.x;      // 0..1
    int bm = blockIdx.y;      // 0..511
    const float* Abase = g_X + (size_t)(bm * 128) * CIN;
    const float* Bbase = g_W + (size_t)(bn * 256) * CIN;

    // staging coords
    int srow = tid >> 3;            // 0..31
    int sk4  = (tid & 7) * 4;       // 0..28

    const int aoff[2] = { AOFF0, AOFF1 };
    const int boff[2] = { BOFF0, BOFF1 };

    float acc[4][8][4];
    #pragma unroll
    for (int i = 0; i < 4; i++)
        #pragma unroll
        for (int j = 0; j < 8; j++)
            #pragma unroll
            for (int q = 0; q < 4; q++) acc[i][j][q] = 0.0f;

    // stage chunk `c` into buffer `buf`
    auto stage = [&](int c, int buf) {
        int k0 = c * KCHUNK;
        #pragma unroll
        for (int i = 0; i < 4; i++) {               // A: 128 rows
            int row = srow + 32 * i;
            cpa16(sb + (uint32_t)(aoff[buf] + row * TSTRIDE + sk4) * 4,
                  Abase + (size_t)row * CIN + k0 + sk4);
        }
        #pragma unroll
        for (int i = 0; i < 8; i++) {               // B: 256 rows
            int row = srow + 32 * i;
            cpa16(sb + (uint32_t)(boff[buf] + row * TSTRIDE + sk4) * 4,
                  Bbase + (size_t)row * CIN + k0 + sk4);
        }
    };

    stage(0, 0);
    CP_COMMIT();

    for (int c = 0; c < NCHUNK; c++) {
        int buf = c & 1;
        if (c + 1 < NCHUNK) {
            stage(c + 1, buf ^ 1);
            CP_COMMIT();
            CP_WAIT(1);
        } else {
            CP_WAIT(0);
        }
        __syncthreads();

        const float* Aw = smem + aoff[buf];
        const float* Bw = smem + boff[buf];
        #pragma unroll
        for (int k8 = 0; k8 < KCHUNK; k8 += 8) {
            uint32_t a[4][4], b[8][2];
            #pragma unroll
            for (int mt = 0; mt < 4; mt++) {
                int rb = warp_m + mt * 16 + g;
                a[mt][0] = __float_as_uint(Aw[rb * TSTRIDE + k8 + tg]);
                a[mt][1] = __float_as_uint(Aw[(rb + 8) * TSTRIDE + k8 + tg]);
                a[mt][2] = __float_as_uint(Aw[rb * TSTRIDE + k8 + tg + 4]);
                a[mt][3] = __float_as_uint(Aw[(rb + 8) * TSTRIDE + k8 + tg + 4]);
            }
            #pragma unroll
            for (int nt = 0; nt < 8; nt++) {
                int nb = warp_n + nt * 8 + g;
                b[nt][0] = __float_as_uint(Bw[nb * TSTRIDE + k8 + tg]);
                b[nt][1] = __float_as_uint(Bw[nb * TSTRIDE + k8 + tg + 4]);
            }
            #pragma unroll
            for (int mt = 0; mt < 4; mt++)
                #pragma unroll
                for (int nt = 0; nt < 8; nt++)
                    mma_tf32(acc[mt][nt][0], acc[mt][nt][1], acc[mt][nt][2], acc[mt][nt][3],
                             a[mt][0], a[mt][1], a[mt][2], a[mt][3],
                             b[nt][0], b[nt][1]);
        }
        __syncthreads();
    }

    // epilogue
    #pragma unroll
    for (int mt = 0; mt < 4; mt++) {
        int row = bm * 128 + warp_m + mt * 16 + g;
        #pragma unroll
        for (int nt = 0; nt < 8; nt++) {
            int col = bn * 256 + warp_n + nt * 8 + 2 * tg;
            float2* p0 = reinterpret_cast<float2*>(g_P + (size_t)row * COUT + col);
            float2* p1 = reinterpret_cast<float2*>(g_P + (size_t)(row + 8) * COUT + col);
            *p0 = make_float2(acc[mt][nt][0], acc[mt][nt][1]);
            *p1 = make_float2(acc[mt][nt][2], acc[mt][nt][3]);
        }
    }
}

// ---------------------------------------------------------------------------
// K3: out[m, o] = max_k P[knn[m,k], o]; also n_xyz gather and n_offset.
// Output layout: [ n_xyz (3*M) | out (M*COUT) | n_offset (1) ]  (fp32)
// g_P loads are float4 (aligned, high MLP); d_out stores scalar (base 3*M
// is not 16B-aligned).
// ---------------------------------------------------------------------------
__global__ void pool_kernel(const float* __restrict__ xyz,
                            const int* __restrict__ samp,
                            const int* __restrict__ knn,
                            const int* __restrict__ offset,
                            float* __restrict__ out,
                            int m_total) {
    int m = blockIdx.x;
    int t = threadIdx.x;           // 128 threads, thread t: channels 4t..4t+3

    const int* kn = knn + (size_t)m * KNN;
    int idx[KNN];
    #pragma unroll
    for (int k = 0; k < KNN; k++) idx[k] = kn[k];

    float4 best = make_float4(-3.4e38f, -3.4e38f, -3.4e38f, -3.4e38f);
    #pragma unroll
    for (int k = 0; k < KNN; k++) {
        float4 v = *reinterpret_cast<const float4*>(g_P + (size_t)idx[k] * COUT + t * 4);
        best.x = fmaxf(best.x, v.x);
        best.y = fmaxf(best.y, v.y);
        best.z = fmaxf(best.z, v.z);
        best.w = fmaxf(best.w, v.w);
    }

    float* osec = out + (size_t)3 * m_total + (size_t)m * COUT + t * 4;
    osec[0] = best.x; osec[1] = best.y; osec[2] = best.z; osec[3] = best.w;

    if (t < 3) {
        out[(size_t)m * 3 + t] = xyz[(size_t)samp[m] * 3 + t];
    }
    if (m == 0 && t == 3) {
        out[(size_t)3 * m_total + (size_t)m_total * COUT] = (float)(offset[0] / 4 + 1);
    }
}

// ---------------------------------------------------------------------------
extern "C" void kernel_launch(void* const* d_in, const int* in_sizes, int n_in,
                              void* d_out, int out_size) {
    const float* xyz   = (const float*)d_in[0];
    const float* feats = (const float*)d_in[1];
    const float* nw    = (const float*)d_in[2];
    const float* nb    = (const float*)d_in[3];
    const float* lw    = (const float*)d_in[4];
    const int*   samp  = (const int*)d_in[5];
    const int*   knn   = (const int*)d_in[6];
    const int*   off   = (const int*)d_in[7];
    float* out = (float*)d_out;

    int M = in_sizes[5];           // 16385

    cudaFuncSetAttribute(gemm_mma_kernel,
                         cudaFuncAttributeMaxDynamicSharedMemorySize,
                         SMEM_GEMM_BYTES);

    wcvt_kernel<<<COUT * CIN / 4 / 256, 256>>>(lw);
    ln_kernel<<<NPTS / 8, 256>>>(feats, nw, nb);

    dim3 ggrid(COUT / 256, NPTS / 128);   // (2, 512), bn fastest
    gemm_mma_kernel<<<ggrid, 256, SMEM_GEMM_BYTES>>>();

    pool_kernel<<<M, 128>>>(xyz, samp, knn, off, out, M);
}

// round 8
// speedup vs baseline: 2.9561x; 1.1660x over previous
#include <cuda_runtime.h>
#include <cuda_fp16.h>
#include <cstdint>

#define NPTS 65536
#define CIN  256
#define COUT 512
#define KNN  16
#define LN_EPS 1e-5f

// Scratch (allocation-free requirement -> __device__ globals)
__device__ float   g_X[(size_t)NPTS * CIN];          // 64 MB: LN'd feats (tf32-rounded)
__device__ float   g_W[(size_t)COUT * CIN];          // 512 KB: tf32-rounded weights
__device__ __half2 g_Ph[(size_t)NPTS * COUT / 2];    // 64 MB: projected feats (fp16)

__device__ __forceinline__ uint32_t smem_to_u32(const void* p) {
    uint32_t a;
    asm("{ .reg .u64 t; cvta.to.shared.u64 t, %1; cvt.u32.u64 %0, t; }" : "=r"(a) : "l"(p));
    return a;
}

__device__ __forceinline__ float cvt_tf32f(float x) {
    uint32_t r;
    asm("cvt.rna.tf32.f32 %0, %1;" : "=r"(r) : "f"(x));
    return __uint_as_float(r);
}

__device__ __forceinline__ void cpa16(uint32_t dst, const float* src) {
    asm volatile("cp.async.cg.shared.global [%0], [%1], 16;" :: "r"(dst), "l"(src));
}
#define CP_COMMIT() asm volatile("cp.async.commit_group;" ::: "memory")
#define CP_WAIT(n)  asm volatile("cp.async.wait_group %0;" :: "n"(n) : "memory")

__device__ __forceinline__ void mma_tf32(float& c0, float& c1, float& c2, float& c3,
                                         uint32_t a0, uint32_t a1, uint32_t a2, uint32_t a3,
                                         uint32_t b0, uint32_t b1) {
    asm volatile(
        "mma.sync.aligned.m16n8k8.row.col.f32.tf32.tf32.f32 "
        "{%0,%1,%2,%3}, {%4,%5,%6,%7}, {%8,%9}, {%0,%1,%2,%3};"
        : "+f"(c0), "+f"(c1), "+f"(c2), "+f"(c3)
        : "r"(a0), "r"(a1), "r"(a2), "r"(a3), "r"(b0), "r"(b1));
}

// ---------------------------------------------------------------------------
// K0: round W to tf32 once.
// ---------------------------------------------------------------------------
__global__ void wcvt_kernel(const float* __restrict__ W) {
    int i = blockIdx.x * 256 + threadIdx.x;             // COUT*CIN/4 = 32768 float4
    float4 v = reinterpret_cast<const float4*>(W)[i];
    v.x = cvt_tf32f(v.x); v.y = cvt_tf32f(v.y);
    v.z = cvt_tf32f(v.z); v.w = cvt_tf32f(v.w);
    reinterpret_cast<float4*>(g_W)[i] = v;
}

// ---------------------------------------------------------------------------
// K1: per-row LayerNorm, output rounded to tf32.  One warp per row.
// ---------------------------------------------------------------------------
__global__ void ln_kernel(const float* __restrict__ feats,
                          const float* __restrict__ w,
                          const float* __restrict__ b) {
    int row  = blockIdx.x * 8 + (threadIdx.x >> 5);
    int lane = threadIdx.x & 31;
    const float4* src = reinterpret_cast<const float4*>(feats) + (size_t)row * (CIN / 4);
    float4 v0 = src[lane];
    float4 v1 = src[lane + 32];

    float s = v0.x + v0.y + v0.z + v0.w + v1.x + v1.y + v1.z + v1.w;
    #pragma unroll
    for (int o = 16; o; o >>= 1) s += __shfl_xor_sync(0xffffffffu, s, o);
    float mu = s * (1.0f / CIN);

    float d0 = v0.x - mu, d1 = v0.y - mu, d2 = v0.z - mu, d3 = v0.w - mu;
    float d4 = v1.x - mu, d5 = v1.y - mu, d6 = v1.z - mu, d7 = v1.w - mu;
    float ss = d0*d0 + d1*d1 + d2*d2 + d3*d3 + d4*d4 + d5*d5 + d6*d6 + d7*d7;
    #pragma unroll
    for (int o = 16; o; o >>= 1) ss += __shfl_xor_sync(0xffffffffu, ss, o);
    float r = rsqrtf(ss * (1.0f / CIN) + LN_EPS);

    const float4* w4 = reinterpret_cast<const float4*>(w);
    const float4* b4 = reinterpret_cast<const float4*>(b);
    float4 W0 = w4[lane], W1 = w4[lane + 32];
    float4 B0 = b4[lane], B1 = b4[lane + 32];

    float4 o0, o1;
    o0.x = cvt_tf32f(d0 * r * W0.x + B0.x);  o0.y = cvt_tf32f(d1 * r * W0.y + B0.y);
    o0.z = cvt_tf32f(d2 * r * W0.z + B0.z);  o0.w = cvt_tf32f(d3 * r * W0.w + B0.w);
    o1.x = cvt_tf32f(d4 * r * W1.x + B1.x);  o1.y = cvt_tf32f(d5 * r * W1.y + B1.y);
    o1.z = cvt_tf32f(d6 * r * W1.z + B1.z);  o1.w = cvt_tf32f(d7 * r * W1.w + B1.w);

    float4* dst = reinterpret_cast<float4*>(g_X) + (size_t)row * (CIN / 4);
    dst[lane]      = o0;
    dst[lane + 32] = o1;
}

// ---------------------------------------------------------------------------
// K2: tf32 mma.sync GEMM.  P = X (NPTS x CIN) @ W^T, output packed fp16.
// CTA tile 128x256, 8 warps of 64x64 (2x4).  cp.async double-buffered chunks.
// grid = (COUT/256, NPTS/128) = (2, 512): bn fastest -> A tiles L2-shared.
// ---------------------------------------------------------------------------
#define KCHUNK 32
#define NCHUNK (CIN / KCHUNK)     // 8
#define TSTRIDE 36
#define AOFF0 0
#define AOFF1 (128 * TSTRIDE)                 // 4608
#define BOFF0 (2 * 128 * TSTRIDE)             // 9216
#define BOFF1 (BOFF0 + 256 * TSTRIDE)         // 18432
#define SMEM_GEMM_FLOATS (BOFF1 + 256 * TSTRIDE)   // 27648
#define SMEM_GEMM_BYTES (SMEM_GEMM_FLOATS * 4)     // 110592

__global__ __launch_bounds__(256, 1) void gemm_mma_kernel() {
    extern __shared__ float smem[];
    uint32_t sb = smem_to_u32(smem);

    int tid  = threadIdx.x;
    int lane = tid & 31;
    int wid  = tid >> 5;
    int g    = lane >> 2;     // 0..7
    int tg   = lane & 3;      // 0..3
    int warp_m = (wid & 1) * 64;
    int warp_n = (wid >> 1) * 64;

    int bn = blockIdx.x;      // 0..1
    int bm = blockIdx.y;      // 0..511
    const float* Abase = g_X + (size_t)(bm * 128) * CIN;
    const float* Bbase = g_W + (size_t)(bn * 256) * CIN;

    int srow = tid >> 3;            // 0..31
    int sk4  = (tid & 7) * 4;       // 0..28

    const int aoff[2] = { AOFF0, AOFF1 };
    const int boff[2] = { BOFF0, BOFF1 };

    float acc[4][8][4];
    #pragma unroll
    for (int i = 0; i < 4; i++)
        #pragma unroll
        for (int j = 0; j < 8; j++)
            #pragma unroll
            for (int q = 0; q < 4; q++) acc[i][j][q] = 0.0f;

    auto stage = [&](int c, int buf) {
        int k0 = c * KCHUNK;
        #pragma unroll
        for (int i = 0; i < 4; i++) {               // A: 128 rows
            int row = srow + 32 * i;
            cpa16(sb + (uint32_t)(aoff[buf] + row * TSTRIDE + sk4) * 4,
                  Abase + (size_t)row * CIN + k0 + sk4);
        }
        #pragma unroll
        for (int i = 0; i < 8; i++) {               // B: 256 rows
            int row = srow + 32 * i;
            cpa16(sb + (uint32_t)(boff[buf] + row * TSTRIDE + sk4) * 4,
                  Bbase + (size_t)row * CIN + k0 + sk4);
        }
    };

    stage(0, 0);
    CP_COMMIT();

    for (int c = 0; c < NCHUNK; c++) {
        int buf = c & 1;
        if (c + 1 < NCHUNK) {
            stage(c + 1, buf ^ 1);
            CP_COMMIT();
            CP_WAIT(1);
        } else {
            CP_WAIT(0);
        }
        __syncthreads();

        const float* Aw = smem + aoff[buf];
        const float* Bw = smem + boff[buf];
        #pragma unroll
        for (int k8 = 0; k8 < KCHUNK; k8 += 8) {
            uint32_t a[4][4], b[8][2];
            #pragma unroll
            for (int mt = 0; mt < 4; mt++) {
                int rb = warp_m + mt * 16 + g;
                a[mt][0] = __float_as_uint(Aw[rb * TSTRIDE + k8 + tg]);
                a[mt][1] = __float_as_uint(Aw[(rb + 8) * TSTRIDE + k8 + tg]);
                a[mt][2] = __float_as_uint(Aw[rb * TSTRIDE + k8 + tg + 4]);
                a[mt][3] = __float_as_uint(Aw[(rb + 8) * TSTRIDE + k8 + tg + 4]);
            }
            #pragma unroll
            for (int nt = 0; nt < 8; nt++) {
                int nb = warp_n + nt * 8 + g;
                b[nt][0] = __float_as_uint(Bw[nb * TSTRIDE + k8 + tg]);
                b[nt][1] = __float_as_uint(Bw[nb * TSTRIDE + k8 + tg + 4]);
            }
            #pragma unroll
            for (int mt = 0; mt < 4; mt++)
                #pragma unroll
                for (int nt = 0; nt < 8; nt++)
                    mma_tf32(acc[mt][nt][0], acc[mt][nt][1], acc[mt][nt][2], acc[mt][nt][3],
                             a[mt][0], a[mt][1], a[mt][2], a[mt][3],
                             b[nt][0], b[nt][1]);
        }
        __syncthreads();
    }

    // epilogue: pack col pairs (2tg, 2tg+1) into half2
    #pragma unroll
    for (int mt = 0; mt < 4; mt++) {
        int row = bm * 128 + warp_m + mt * 16 + g;
        #pragma unroll
        for (int nt = 0; nt < 8; nt++) {
            int col = bn * 256 + warp_n + nt * 8 + 2 * tg;   // even
            g_Ph[(size_t)row * (COUT / 2) + (col >> 1)] =
                __floats2half2_rn(acc[mt][nt][0], acc[mt][nt][1]);
            g_Ph[(size_t)(row + 8) * (COUT / 2) + (col >> 1)] =
                __floats2half2_rn(acc[mt][nt][2], acc[mt][nt][3]);
        }
    }
}

// ---------------------------------------------------------------------------
// K3: out[m, o] = max_k P[knn[m,k], o]; also n_xyz gather and n_offset.
// P is fp16 (L2-resident, 64 MB).  Thread t: channels 4t..4t+3 (2 half2).
// Output layout: [ n_xyz (3*M) | out (M*COUT) | n_offset (1) ]  (fp32, scalar
// stores: the out section base 3*M is not 16B-aligned).
// ---------------------------------------------------------------------------
__global__ void pool_kernel(const float* __restrict__ xyz,
                            const int* __restrict__ samp,
                            const int* __restrict__ knn,
                            const int* __restrict__ offset,
                            float* __restrict__ out,
                            int m_total) {
    int m = blockIdx.x;
    int t = threadIdx.x;           // 128 threads

    const int* kn = knn + (size_t)m * KNN;
    int idx[KNN];
    #pragma unroll
    for (int k = 0; k < KNN; k++) idx[k] = kn[k];

    uint2 v0 = *reinterpret_cast<const uint2*>(g_Ph + (size_t)idx[0] * (COUT / 2) + 2 * t);
    __half2 b0 = *reinterpret_cast<__half2*>(&v0.x);
    __half2 b1 = *reinterpret_cast<__half2*>(&v0.y);
    #pragma unroll
    for (int k = 1; k < KNN; k++) {
        uint2 v = *reinterpret_cast<const uint2*>(g_Ph + (size_t)idx[k] * (COUT / 2) + 2 * t);
        b0 = __hmax2(b0, *reinterpret_cast<__half2*>(&v.x));
        b1 = __hmax2(b1, *reinterpret_cast<__half2*>(&v.y));
    }

    float2 f0 = __half22float2(b0);
    float2 f1 = __half22float2(b1);
    float* osec = out + (size_t)3 * m_total + (size_t)m * COUT + t * 4;
    osec[0] = f0.x; osec[1] = f0.y; osec[2] = f1.x; osec[3] = f1.y;

    if (t < 3) {
        out[(size_t)m * 3 + t] = xyz[(size_t)samp[m] * 3 + t];
    }
    if (m == 0 && t == 3) {
        out[(size_t)3 * m_total + (size_t)m_total * COUT] = (float)(offset[0] / 4 + 1);
    }
}

// ---------------------------------------------------------------------------
extern "C" void kernel_launch(void* const* d_in, const int* in_sizes, int n_in,
                              void* d_out, int out_size) {
    const float* xyz   = (const float*)d_in[0];
    const float* feats = (const float*)d_in[1];
    const float* nw    = (const float*)d_in[2];
    const float* nb    = (const float*)d_in[3];
    const float* lw    = (const float*)d_in[4];
    const int*   samp  = (const int*)d_in[5];
    const int*   knn   = (const int*)d_in[6];
    const int*   off   = (const int*)d_in[7];
    float* out = (float*)d_out;

    int M = in_sizes[5];           // 16385

    cudaFuncSetAttribute(gemm_mma_kernel,
                         cudaFuncAttributeMaxDynamicSharedMemorySize,
                         SMEM_GEMM_BYTES);

    wcvt_kernel<<<COUT * CIN / 4 / 256, 256>>>(lw);
    ln_kernel<<<NPTS / 8, 256>>>(feats, nw, nb);

    dim3 ggrid(COUT / 256, NPTS / 128);   // (2, 512), bn fastest
    gemm_mma_kernel<<<ggrid, 256, SMEM_GEMM_BYTES>>>();

    pool_kernel<<<M, 128>>>(xyz, samp, knn, off, out, M);
}

// round 9
// speedup vs baseline: 4.0486x; 1.3696x over previous
#include <cuda_runtime.h>
#include <cuda_fp16.h>
#include <cstdint>

#define NPTS 65536
#define CIN  256
#define COUT 512
#define KNN  16
#define LN_EPS 1e-5f

// Scratch (allocation-free requirement -> __device__ globals)
__device__ __half2 g_Xh[(size_t)NPTS * CIN / 2];     // 32 MB: LN'd feats (fp16)
__device__ __half2 g_Wh[(size_t)COUT * CIN / 2];     // 256 KB: fp16 weights
__device__ __half2 g_Ph[(size_t)NPTS * COUT / 2];    // 64 MB: projected feats (fp16)

__device__ __forceinline__ uint32_t smem_to_u32(const void* p) {
    uint32_t a;
    asm("{ .reg .u64 t; cvta.to.shared.u64 t, %1; cvt.u32.u64 %0, t; }" : "=r"(a) : "l"(p));
    return a;
}

__device__ __forceinline__ void cpa16(uint32_t dst, const void* src) {
    asm volatile("cp.async.cg.shared.global [%0], [%1], 16;" :: "r"(dst), "l"(src));
}
#define CP_COMMIT() asm volatile("cp.async.commit_group;" ::: "memory")
#define CP_WAIT(n)  asm volatile("cp.async.wait_group %0;" :: "n"(n) : "memory")

__device__ __forceinline__ void mma_f16(float& c0, float& c1, float& c2, float& c3,
                                        uint32_t a0, uint32_t a1, uint32_t a2, uint32_t a3,
                                        uint32_t b0, uint32_t b1) {
    asm volatile(
        "mma.sync.aligned.m16n8k16.row.col.f32.f16.f16.f32 "
        "{%0,%1,%2,%3}, {%4,%5,%6,%7}, {%8,%9}, {%0,%1,%2,%3};"
        : "+f"(c0), "+f"(c1), "+f"(c2), "+f"(c3)
        : "r"(a0), "r"(a1), "r"(a2), "r"(a3), "r"(b0), "r"(b1));
}

// ---------------------------------------------------------------------------
// K0: convert W to fp16 once.  COUT*CIN/4 = 32768 float4 -> uint2 (4 halves).
// ---------------------------------------------------------------------------
__global__ void wcvt_kernel(const float* __restrict__ W) {
    int i = blockIdx.x * 256 + threadIdx.x;
    float4 v = reinterpret_cast<const float4*>(W)[i];
    __half2 h0 = __floats2half2_rn(v.x, v.y);
    __half2 h1 = __floats2half2_rn(v.z, v.w);
    g_Wh[2 * i]     = h0;
    g_Wh[2 * i + 1] = h1;
}

// ---------------------------------------------------------------------------
// K1: per-row LayerNorm, output fp16.  One warp per row.
// ---------------------------------------------------------------------------
__global__ void ln_kernel(const float* __restrict__ feats,
                          const float* __restrict__ w,
                          const float* __restrict__ b) {
    int row  = blockIdx.x * 8 + (threadIdx.x >> 5);
    int lane = threadIdx.x & 31;
    const float4* src = reinterpret_cast<const float4*>(feats) + (size_t)row * (CIN / 4);
    float4 v0 = src[lane];
    float4 v1 = src[lane + 32];

    float s = v0.x + v0.y + v0.z + v0.w + v1.x + v1.y + v1.z + v1.w;
    #pragma unroll
    for (int o = 16; o; o >>= 1) s += __shfl_xor_sync(0xffffffffu, s, o);
    float mu = s * (1.0f / CIN);

    float d0 = v0.x - mu, d1 = v0.y - mu, d2 = v0.z - mu, d3 = v0.w - mu;
    float d4 = v1.x - mu, d5 = v1.y - mu, d6 = v1.z - mu, d7 = v1.w - mu;
    float ss = d0*d0 + d1*d1 + d2*d2 + d3*d3 + d4*d4 + d5*d5 + d6*d6 + d7*d7;
    #pragma unroll
    for (int o = 16; o; o >>= 1) ss += __shfl_xor_sync(0xffffffffu, ss, o);
    float r = rsqrtf(ss * (1.0f / CIN) + LN_EPS);

    const float4* w4 = reinterpret_cast<const float4*>(w);
    const float4* b4 = reinterpret_cast<const float4*>(b);
    float4 W0 = w4[lane], W1 = w4[lane + 32];
    float4 B0 = b4[lane], B1 = b4[lane + 32];

    __half2 h0 = __floats2half2_rn(d0 * r * W0.x + B0.x, d1 * r * W0.y + B0.y);
    __half2 h1 = __floats2half2_rn(d2 * r * W0.z + B0.z, d3 * r * W0.w + B0.w);
    __half2 h2 = __floats2half2_rn(d4 * r * W1.x + B1.x, d5 * r * W1.y + B1.y);
    __half2 h3 = __floats2half2_rn(d6 * r * W1.z + B1.z, d7 * r * W1.w + B1.w);

    __half2* dst = g_Xh + (size_t)row * (CIN / 2);
    dst[2 * lane]          = h0;
    dst[2 * lane + 1]      = h1;
    dst[2 * lane + 64]     = h2;
    dst[2 * lane + 64 + 1] = h3;
}

// ---------------------------------------------------------------------------
// K2: fp16 mma.sync m16n8k16 GEMM.  P = X (NPTS x CIN) @ W^T, output fp16.
// CTA tile 128x256, 8 warps of 64x64 (2x4).  K chunks of 64 halves, dbl-buf.
// grid = (COUT/256, NPTS/128) = (2, 512): bn fastest -> A tiles L2-shared.
// Smem rows: stride 36 half2 (144 B) -> 16B-aligned rows, conflict-free LDS.
// ---------------------------------------------------------------------------
#define KCHUNK 64                  // halves per chunk
#define NCHUNK (CIN / KCHUNK)      // 4
#define ST 36                      // row stride in half2 units
#define AOFF0 0
#define AOFF1 (128 * ST)                      // 4608
#define BOFF0 (2 * 128 * ST)                  // 9216
#define BOFF1 (BOFF0 + 256 * ST)              // 18432
#define SMEM_GEMM_U32 (BOFF1 + 256 * ST)      // 27648 half2
#define SMEM_GEMM_BYTES (SMEM_GEMM_U32 * 4)   // 110592

__global__ __launch_bounds__(256, 1) void gemm_mma_kernel() {
    extern __shared__ uint32_t smem[];     // half2 units
    uint32_t sb = smem_to_u32(smem);

    int tid  = threadIdx.x;
    int lane = tid & 31;
    int wid  = tid >> 5;
    int g    = lane >> 2;     // 0..7
    int tg   = lane & 3;      // 0..3
    int warp_m = (wid & 1) * 64;
    int warp_n = (wid >> 1) * 64;

    int bn = blockIdx.x;      // 0..1
    int bm = blockIdx.y;      // 0..511
    const __half2* Abase = g_Xh + (size_t)(bm * 128) * (CIN / 2);
    const __half2* Bbase = g_Wh + (size_t)(bn * 256) * (CIN / 2);

    int srow = tid >> 3;            // 0..31
    int sseg = tid & 7;             // 16B segment within 128B row chunk

    const int aoff[2] = { AOFF0, AOFF1 };
    const int boff[2] = { BOFF0, BOFF1 };

    float acc[4][8][4];
    #pragma unroll
    for (int i = 0; i < 4; i++)
        #pragma unroll
        for (int j = 0; j < 8; j++)
            #pragma unroll
            for (int q = 0; q < 4; q++) acc[i][j][q] = 0.0f;

    auto stage = [&](int c, int buf) {
        int k2 = c * (KCHUNK / 2);              // half2 offset in source row
        #pragma unroll
        for (int i = 0; i < 4; i++) {           // A: 128 rows x 8 segs
            int row = srow + 32 * i;
            cpa16(sb + (uint32_t)(aoff[buf] + row * ST + sseg * 4) * 4,
                  Abase + (size_t)row * (CIN / 2) + k2 + sseg * 4);
        }
        #pragma unroll
        for (int i = 0; i < 8; i++) {           // B: 256 rows x 8 segs
            int row = srow + 32 * i;
            cpa16(sb + (uint32_t)(boff[buf] + row * ST + sseg * 4) * 4,
                  Bbase + (size_t)row * (CIN / 2) + k2 + sseg * 4);
        }
    };

    stage(0, 0);
    CP_COMMIT();

    for (int c = 0; c < NCHUNK; c++) {
        int buf = c & 1;
        if (c + 1 < NCHUNK) {
            stage(c + 1, buf ^ 1);
            CP_COMMIT();
            CP_WAIT(1);
        } else {
            CP_WAIT(0);
        }
        __syncthreads();

        const uint32_t* Aw = smem + aoff[buf];
        const uint32_t* Bw = smem + boff[buf];
        #pragma unroll
        for (int s = 0; s < 4; s++) {            // 4 k16 steps per 64-half chunk
            int k2 = 8 * s;                      // half2 offset of this k16 step
            uint32_t a[4][4], b[8][2];
            #pragma unroll
            for (int mt = 0; mt < 4; mt++) {
                int rb = warp_m + mt * 16 + g;
                a[mt][0] = Aw[rb * ST + k2 + tg];
                a[mt][1] = Aw[(rb + 8) * ST + k2 + tg];
                a[mt][2] = Aw[rb * ST + k2 + tg + 4];
                a[mt][3] = Aw[(rb + 8) * ST + k2 + tg + 4];
            }
            #pragma unroll
            for (int nt = 0; nt < 8; nt++) {
                int nb = warp_n + nt * 8 + g;
                b[nt][0] = Bw[nb * ST + k2 + tg];
                b[nt][1] = Bw[nb * ST + k2 + tg + 4];
            }
            #pragma unroll
            for (int mt = 0; mt < 4; mt++)
                #pragma unroll
                for (int nt = 0; nt < 8; nt++)
                    mma_f16(acc[mt][nt][0], acc[mt][nt][1], acc[mt][nt][2], acc[mt][nt][3],
                            a[mt][0], a[mt][1], a[mt][2], a[mt][3],
                            b[nt][0], b[nt][1]);
        }
        __syncthreads();
    }

    // epilogue: pack col pairs (2tg, 2tg+1) into half2
    #pragma unroll
    for (int mt = 0; mt < 4; mt++) {
        int row = bm * 128 + warp_m + mt * 16 + g;
        #pragma unroll
        for (int nt = 0; nt < 8; nt++) {
            int col = bn * 256 + warp_n + nt * 8 + 2 * tg;   // even
            g_Ph[(size_t)row * (COUT / 2) + (col >> 1)] =
                __floats2half2_rn(acc[mt][nt][0], acc[mt][nt][1]);
            g_Ph[(size_t)(row + 8) * (COUT / 2) + (col >> 1)] =
                __floats2half2_rn(acc[mt][nt][2], acc[mt][nt][3]);
        }
    }
}

// ---------------------------------------------------------------------------
// K3: out[m, o] = max_k P[knn[m,k], o]; also n_xyz gather and n_offset.
// P is fp16 (L2-resident, 64 MB).  Thread t: channels 4t..4t+3 (2 half2).
// Output layout: [ n_xyz (3*M) | out (M*COUT) | n_offset (1) ]  (fp32, scalar
// stores: the out section base 3*M is not 16B-aligned).
// ---------------------------------------------------------------------------
__global__ void pool_kernel(const float* __restrict__ xyz,
                            const int* __restrict__ samp,
                            const int* __restrict__ knn,
                            const int* __restrict__ offset,
                            float* __restrict__ out,
                            int m_total) {
    int m = blockIdx.x;
    int t = threadIdx.x;           // 128 threads

    const int* kn = knn + (size_t)m * KNN;
    int idx[KNN];
    #pragma unroll
    for (int k = 0; k < KNN; k++) idx[k] = kn[k];

    uint2 v0 = *reinterpret_cast<const uint2*>(g_Ph + (size_t)idx[0] * (COUT / 2) + 2 * t);
    __half2 b0 = *reinterpret_cast<__half2*>(&v0.x);
    __half2 b1 = *reinterpret_cast<__half2*>(&v0.y);
    #pragma unroll
    for (int k = 1; k < KNN; k++) {
        uint2 v = *reinterpret_cast<const uint2*>(g_Ph + (size_t)idx[k] * (COUT / 2) + 2 * t);
        b0 = __hmax2(b0, *reinterpret_cast<__half2*>(&v.x));
        b1 = __hmax2(b1, *reinterpret_cast<__half2*>(&v.y));
    }

    float2 f0 = __half22float2(b0);
    float2 f1 = __half22float2(b1);
    float* osec = out + (size_t)3 * m_total + (size_t)m * COUT + t * 4;
    osec[0] = f0.x; osec[1] = f0.y; osec[2] = f1.x; osec[3] = f1.y;

    if (t < 3) {
        out[(size_t)m * 3 + t] = xyz[(size_t)samp[m] * 3 + t];
    }
    if (m == 0 && t == 3) {
        out[(size_t)3 * m_total + (size_t)m_total * COUT] = (float)(offset[0] / 4 + 1);
    }
}

// ---------------------------------------------------------------------------
extern "C" void kernel_launch(void* const* d_in, const int* in_sizes, int n_in,
                              void* d_out, int out_size) {
    const float* xyz   = (const float*)d_in[0];
    const float* feats = (const float*)d_in[1];
    const float* nw    = (const float*)d_in[2];
    const float* nb    = (const float*)d_in[3];
    const float* lw    = (const float*)d_in[4];
    const int*   samp  = (const int*)d_in[5];
    const int*   knn   = (const int*)d_in[6];
    const int*   off   = (const int*)d_in[7];
    float* out = (float*)d_out;

    int M = in_sizes[5];           // 16385

    cudaFuncSetAttribute(gemm_mma_kernel,
                         cudaFuncAttributeMaxDynamicSharedMemorySize,
                         SMEM_GEMM_BYTES);

    wcvt_kernel<<<COUT * CIN / 4 / 256, 256>>>(lw);
    ln_kernel<<<NPTS / 8, 256>>>(feats, nw, nb);

    dim3 ggrid(COUT / 256, NPTS / 128);   // (2, 512), bn fastest
    gemm_mma_kernel<<<ggrid, 256, SMEM_GEMM_BYTES>>>();

    pool_kernel<<<M, 128>>>(xyz, samp, knn, off, out, M);
}

// round 10
// speedup vs baseline: 4.0960x; 1.0117x over previous
#include <cuda_runtime.h>
#include <cuda_fp16.h>
#include <cstdint>

#define NPTS 65536
#define CIN  256
#define COUT 512
#define KNN  16
#define LN_EPS 1e-5f

// Scratch (allocation-free requirement -> __device__ globals)
__device__ __half2 g_Xh[(size_t)NPTS * CIN / 2];     // 32 MB: LN'd feats (fp16)
__device__ __half2 g_Wh[(size_t)COUT * CIN / 2];     // 256 KB: fp16 weights
__device__ __half2 g_Ph[(size_t)NPTS * COUT / 2];    // 64 MB: projected feats (fp16)

__device__ __forceinline__ uint32_t smem_to_u32(const void* p) {
    uint32_t a;
    asm("{ .reg .u64 t; cvta.to.shared.u64 t, %1; cvt.u32.u64 %0, t; }" : "=r"(a) : "l"(p));
    return a;
}

__device__ __forceinline__ void cpa16(uint32_t dst, const void* src) {
    asm volatile("cp.async.cg.shared.global [%0], [%1], 16;" :: "r"(dst), "l"(src));
}
#define CP_COMMIT() asm volatile("cp.async.commit_group;" ::: "memory")
#define CP_WAIT(n)  asm volatile("cp.async.wait_group %0;" :: "n"(n) : "memory")

__device__ __forceinline__ void mma_f16(float& c0, float& c1, float& c2, float& c3,
                                        uint32_t a0, uint32_t a1, uint32_t a2, uint32_t a3,
                                        uint32_t b0, uint32_t b1) {
    asm volatile(
        "mma.sync.aligned.m16n8k16.row.col.f32.f16.f16.f32 "
        "{%0,%1,%2,%3}, {%4,%5,%6,%7}, {%8,%9}, {%0,%1,%2,%3};"
        : "+f"(c0), "+f"(c1), "+f"(c2), "+f"(c3)
        : "r"(a0), "r"(a1), "r"(a2), "r"(a3), "r"(b0), "r"(b1));
}

// ---------------------------------------------------------------------------
// K1: per-row LayerNorm -> fp16 (one warp per row, blocks 0..8191);
//     blocks 8192..8255 convert W to fp16 instead (whole-block branch).
// ---------------------------------------------------------------------------
#define LN_BLOCKS (NPTS / 8)          // 8192
#define WCVT_BLOCKS 64                // 64*256*2 float4 = 32768 = COUT*CIN/4

__global__ void ln_kernel(const float* __restrict__ feats,
                          const float* __restrict__ w,
                          const float* __restrict__ b,
                          const float* __restrict__ W) {
    if (blockIdx.x >= LN_BLOCKS) {
        // W conversion: 64 blocks x 256 threads x 2 float4
        int base = (blockIdx.x - LN_BLOCKS) * 512 + threadIdx.x;
        #pragma unroll
        for (int r = 0; r < 2; r++) {
            int i = base + r * 256;
            float4 v = reinterpret_cast<const float4*>(W)[i];
            g_Wh[2 * i]     = __floats2half2_rn(v.x, v.y);
            g_Wh[2 * i + 1] = __floats2half2_rn(v.z, v.w);
        }
        return;
    }

    int row  = blockIdx.x * 8 + (threadIdx.x >> 5);
    int lane = threadIdx.x & 31;
    const float4* src = reinterpret_cast<const float4*>(feats) + (size_t)row * (CIN / 4);
    float4 v0 = src[lane];
    float4 v1 = src[lane + 32];

    float s = v0.x + v0.y + v0.z + v0.w + v1.x + v1.y + v1.z + v1.w;
    #pragma unroll
    for (int o = 16; o; o >>= 1) s += __shfl_xor_sync(0xffffffffu, s, o);
    float mu = s * (1.0f / CIN);

    float d0 = v0.x - mu, d1 = v0.y - mu, d2 = v0.z - mu, d3 = v0.w - mu;
    float d4 = v1.x - mu, d5 = v1.y - mu, d6 = v1.z - mu, d7 = v1.w - mu;
    float ss = d0*d0 + d1*d1 + d2*d2 + d3*d3 + d4*d4 + d5*d5 + d6*d6 + d7*d7;
    #pragma unroll
    for (int o = 16; o; o >>= 1) ss += __shfl_xor_sync(0xffffffffu, ss, o);
    float r = rsqrtf(ss * (1.0f / CIN) + LN_EPS);

    const float4* w4 = reinterpret_cast<const float4*>(w);
    const float4* b4 = reinterpret_cast<const float4*>(b);
    float4 W0 = w4[lane], W1 = w4[lane + 32];
    float4 B0 = b4[lane], B1 = b4[lane + 32];

    __half2 h0 = __floats2half2_rn(d0 * r * W0.x + B0.x, d1 * r * W0.y + B0.y);
    __half2 h1 = __floats2half2_rn(d2 * r * W0.z + B0.z, d3 * r * W0.w + B0.w);
    __half2 h2 = __floats2half2_rn(d4 * r * W1.x + B1.x, d5 * r * W1.y + B1.y);
    __half2 h3 = __floats2half2_rn(d6 * r * W1.z + B1.z, d7 * r * W1.w + B1.w);

    __half2* dst = g_Xh + (size_t)row * (CIN / 2);
    dst[2 * lane]          = h0;
    dst[2 * lane + 1]      = h1;
    dst[2 * lane + 64]     = h2;
    dst[2 * lane + 64 + 1] = h3;
}

// ---------------------------------------------------------------------------
// K2: fp16 mma.sync m16n8k16 GEMM.  P = X (NPTS x CIN) @ W^T, output fp16.
// CTA tile 128x256, 8 warps of 64x64 (2x4).  K chunks of 64 halves, dbl-buf.
// grid = (COUT/256, NPTS/128) = (2, 512): bn fastest -> A tiles L2-shared.
// Smem rows: stride 36 half2 (144 B) -> 16B-aligned rows, conflict-free LDS.
// ---------------------------------------------------------------------------
#define KCHUNK 64                  // halves per chunk
#define NCHUNK (CIN / KCHUNK)      // 4
#define ST 36                      // row stride in half2 units
#define AOFF0 0
#define AOFF1 (128 * ST)                      // 4608
#define BOFF0 (2 * 128 * ST)                  // 9216
#define BOFF1 (BOFF0 + 256 * ST)              // 18432
#define SMEM_GEMM_U32 (BOFF1 + 256 * ST)      // 27648 half2
#define SMEM_GEMM_BYTES (SMEM_GEMM_U32 * 4)   // 110592

__global__ __launch_bounds__(256, 1) void gemm_mma_kernel() {
    extern __shared__ uint32_t smem[];     // half2 units
    uint32_t sb = smem_to_u32(smem);

    int tid  = threadIdx.x;
    int lane = tid & 31;
    int wid  = tid >> 5;
    int g    = lane >> 2;     // 0..7
    int tg   = lane & 3;      // 0..3
    int warp_m = (wid & 1) * 64;
    int warp_n = (wid >> 1) * 64;

    int bn = blockIdx.x;      // 0..1
    int bm = blockIdx.y;      // 0..511
    const __half2* Abase = g_Xh + (size_t)(bm * 128) * (CIN / 2);
    const __half2* Bbase = g_Wh + (size_t)(bn * 256) * (CIN / 2);

    int srow = tid >> 3;            // 0..31
    int sseg = tid & 7;             // 16B segment within 128B row chunk

    const int aoff[2] = { AOFF0, AOFF1 };
    const int boff[2] = { BOFF0, BOFF1 };

    float acc[4][8][4];
    #pragma unroll
    for (int i = 0; i < 4; i++)
        #pragma unroll
        for (int j = 0; j < 8; j++)
            #pragma unroll
            for (int q = 0; q < 4; q++) acc[i][j][q] = 0.0f;

    auto stage = [&](int c, int buf) {
        int k2 = c * (KCHUNK / 2);              // half2 offset in source row
        #pragma unroll
        for (int i = 0; i < 4; i++) {           // A: 128 rows x 8 segs
            int row = srow + 32 * i;
            cpa16(sb + (uint32_t)(aoff[buf] + row * ST + sseg * 4) * 4,
                  Abase + (size_t)row * (CIN / 2) + k2 + sseg * 4);
        }
        #pragma unroll
        for (int i = 0; i < 8; i++) {           // B: 256 rows x 8 segs
            int row = srow + 32 * i;
            cpa16(sb + (uint32_t)(boff[buf] + row * ST + sseg * 4) * 4,
                  Bbase + (size_t)row * (CIN / 2) + k2 + sseg * 4);
        }
    };

    stage(0, 0);
    CP_COMMIT();

    for (int c = 0; c < NCHUNK; c++) {
        int buf = c & 1;
        if (c + 1 < NCHUNK) {
            stage(c + 1, buf ^ 1);
            CP_COMMIT();
            CP_WAIT(1);
        } else {
            CP_WAIT(0);
        }
        __syncthreads();

        const uint32_t* Aw = smem + aoff[buf];
        const uint32_t* Bw = smem + boff[buf];
        #pragma unroll
        for (int s = 0; s < 4; s++) {            // 4 k16 steps per 64-half chunk
            int k2 = 8 * s;                      // half2 offset of this k16 step
            uint32_t a[4][4], b[8][2];
            #pragma unroll
            for (int mt = 0; mt < 4; mt++) {
                int rb = warp_m + mt * 16 + g;
                a[mt][0] = Aw[rb * ST + k2 + tg];
                a[mt][1] = Aw[(rb + 8) * ST + k2 + tg];
                a[mt][2] = Aw[rb * ST + k2 + tg + 4];
                a[mt][3] = Aw[(rb + 8) * ST + k2 + tg + 4];
            }
            #pragma unroll
            for (int nt = 0; nt < 8; nt++) {
                int nb = warp_n + nt * 8 + g;
                b[nt][0] = Bw[nb * ST + k2 + tg];
                b[nt][1] = Bw[nb * ST + k2 + tg + 4];
            }
            #pragma unroll
            for (int mt = 0; mt < 4; mt++)
                #pragma unroll
                for (int nt = 0; nt < 8; nt++)
                    mma_f16(acc[mt][nt][0], acc[mt][nt][1], acc[mt][nt][2], acc[mt][nt][3],
                            a[mt][0], a[mt][1], a[mt][2], a[mt][3],
                            b[nt][0], b[nt][1]);
        }
        __syncthreads();
    }

    // epilogue: pack col pairs (2tg, 2tg+1) into half2
    #pragma unroll
    for (int mt = 0; mt < 4; mt++) {
        int row = bm * 128 + warp_m + mt * 16 + g;
        #pragma unroll
        for (int nt = 0; nt < 8; nt++) {
            int col = bn * 256 + warp_n + nt * 8 + 2 * tg;   // even
            g_Ph[(size_t)row * (COUT / 2) + (col >> 1)] =
                __floats2half2_rn(acc[mt][nt][0], acc[mt][nt][1]);
            g_Ph[(size_t)(row + 8) * (COUT / 2) + (col >> 1)] =
                __floats2half2_rn(acc[mt][nt][2], acc[mt][nt][3]);
        }
    }
}

// ---------------------------------------------------------------------------
// K3: out[m, o] = max_k P[knn[m,k], o]; also n_xyz gather and n_offset.
// 2 m-values per block (128 threads: 64 per m, uint4 = 8 channels each).
// knn indices staged once through smem.
// Output layout: [ n_xyz (3*M) | out (M*COUT) | n_offset (1) ]  (fp32, scalar
// stores: the out section base 3*M is not 16B-aligned).
// ---------------------------------------------------------------------------
__global__ void pool_kernel(const float* __restrict__ xyz,
                            const int* __restrict__ samp,
                            const int* __restrict__ knn,
                            const int* __restrict__ offset,
                            float* __restrict__ out,
                            int m_total) {
    __shared__ int sidx[2 * KNN];
    int m0 = blockIdx.x * 2;
    int t  = threadIdx.x;          // 0..127

    if (t < 2 * KNN) {
        int mm = m0 + (t >> 4);
        sidx[t] = (mm < m_total) ? knn[(size_t)mm * KNN + (t & 15)] : 0;
    }
    __syncthreads();

    int half = t >> 6;             // which m
    int c    = t & 63;             // uint4 group: channels 8c..8c+7
    int m    = m0 + half;
    if (m < m_total) {
        const int* kn = sidx + half * KNN;

        const uint4* r0 = reinterpret_cast<const uint4*>(
            g_Ph + (size_t)kn[0] * (COUT / 2)) + c;
        uint4 v = *r0;
        __half2 b0 = *reinterpret_cast<__half2*>(&v.x);
        __half2 b1 = *reinterpret_cast<__half2*>(&v.y);
        __half2 b2 = *reinterpret_cast<__half2*>(&v.z);
        __half2 b3 = *reinterpret_cast<__half2*>(&v.w);
        #pragma unroll
        for (int k = 1; k < KNN; k++) {
            uint4 w = *(reinterpret_cast<const uint4*>(
                g_Ph + (size_t)kn[k] * (COUT / 2)) + c);
            b0 = __hmax2(b0, *reinterpret_cast<__half2*>(&w.x));
            b1 = __hmax2(b1, *reinterpret_cast<__half2*>(&w.y));
            b2 = __hmax2(b2, *reinterpret_cast<__half2*>(&w.z));
            b3 = __hmax2(b3, *reinterpret_cast<__half2*>(&w.w));
        }

        float2 f0 = __half22float2(b0);
        float2 f1 = __half22float2(b1);
        float2 f2 = __half22float2(b2);
        float2 f3 = __half22float2(b3);
        float* osec = out + (size_t)3 * m_total + (size_t)m * COUT + c * 8;
        osec[0] = f0.x; osec[1] = f0.y; osec[2] = f1.x; osec[3] = f1.y;
        osec[4] = f2.x; osec[5] = f2.y; osec[6] = f3.x; osec[7] = f3.y;

        if (c < 3) {
            out[(size_t)m * 3 + c] = xyz[(size_t)samp[m] * 3 + c];
        }
        if (m == 0 && c == 3) {
            out[(size_t)3 * m_total + (size_t)m_total * COUT] = (float)(offset[0] / 4 + 1);
        }
    }
}

// ---------------------------------------------------------------------------
extern "C" void kernel_launch(void* const* d_in, const int* in_sizes, int n_in,
                              void* d_out, int out_size) {
    const float* xyz   = (const float*)d_in[0];
    const float* feats = (const float*)d_in[1];
    const float* nw    = (const float*)d_in[2];
    const float* nb    = (const float*)d_in[3];
    const float* lw    = (const float*)d_in[4];
    const int*   samp  = (const int*)d_in[5];
    const int*   knn   = (const int*)d_in[6];
    const int*   off   = (const int*)d_in[7];
    float* out = (float*)d_out;

    int M = in_sizes[5];           // 16385

    cudaFuncSetAttribute(gemm_mma_kernel,
                         cudaFuncAttributeMaxDynamicSharedMemorySize,
                         SMEM_GEMM_BYTES);

    ln_kernel<<<LN_BLOCKS + WCVT_BLOCKS, 256>>>(feats, nw, nb, lw);

    dim3 ggrid(COUT / 256, NPTS / 128);   // (2, 512), bn fastest
    gemm_mma_kernel<<<ggrid, 256, SMEM_GEMM_BYTES>>>();

    pool_kernel<<<(M + 1) / 2, 128>>>(xyz, samp, knn, off, out, M);
}